// round 5
// baseline (speedup 1.0000x reference)
#include <cuda_runtime.h>
#include <cstdint>
#include <cstddef>

#define NMAX 50000
#define EMAX 600000
#define D 128

// Scratch (no allocations allowed -> __device__ globals).
__device__ __align__(16) float g_dinv[NMAX];
__device__ __align__(16) float g_g1[NMAX * D];     // g1 = (x@W1)*dinv[row]
__device__ __align__(16) float g_agg1[NMAX * D];   // g1[c] + sum g1[src]
__device__ __align__(16) float g_x1[NMAX * D];     // relu(dinv*agg1 + b1)
__device__ __align__(16) float g_g2[NMAX * D];
__device__ __align__(16) float g_agg2[NMAX * D];

// CSR (by destination)
__device__ int g_cnt[NMAX];
__device__ int g_wr[NMAX];
__device__ int g_rowptr[NMAX + 1];
__device__ int g_srcidx[EMAX];

// ---------------------------------------------------------------------------
// CSR build.  edge_index is INT32 (JAX x64 disabled coerces jnp.int64->int32).
// ---------------------------------------------------------------------------
__global__ void cnt_zero_kernel(int n) {
    int i = blockIdx.x * blockDim.x + threadIdx.x;
    if (i < n) g_cnt[i] = 0;
}

__global__ void hist_kernel(const int* __restrict__ ei, int E, int n) {
    int e = blockIdx.x * blockDim.x + threadIdx.x;
    if (e < E) {
        int c = ei[E + e];                      // col (destination)
        if ((unsigned)c < (unsigned)n) atomicAdd(&g_cnt[c], 1);
    }
}

// Single block, 1024 threads: exclusive scan of g_cnt -> rowptr, wr; dinv.
__global__ __launch_bounds__(1024) void scan_kernel(int n) {
    __shared__ int s[1024];
    const int t = threadIdx.x;
    const int C = (n + 1023) / 1024;
    const int start = t * C;
    const int end = min(start + C, n);

    int sum = 0;
    for (int i = start; i < end; i++) sum += g_cnt[i];
    s[t] = sum;
    __syncthreads();

    // Hillis-Steele inclusive scan
    for (int off = 1; off < 1024; off <<= 1) {
        int v = s[t];
        int o = (t >= off) ? s[t - off] : 0;
        __syncthreads();
        s[t] = v + o;
        __syncthreads();
    }

    int run = s[t] - sum;  // exclusive base for this chunk
    for (int i = start; i < end; i++) {
        g_rowptr[i] = run;
        g_wr[i] = run;
        g_dinv[i] = rsqrtf((float)(g_cnt[i] + 1));  // +1 for self loop
        run += g_cnt[i];
    }
    if (t == 0) g_rowptr[n] = s[1023];
}

__global__ void place_kernel(const int* __restrict__ ei, int E, int n) {
    int e = blockIdx.x * blockDim.x + threadIdx.x;
    if (e < E) {
        int c = ei[E + e];
        int r = ei[e];
        if ((unsigned)c < (unsigned)n && (unsigned)r < (unsigned)n) {
            int p = atomicAdd(&g_wr[c], 1);
            g_srcidx[p] = r;
        }
    }
}

// ---------------------------------------------------------------------------
// Gather aggregation: one warp per node. agg[c] = g[c] + sum_{in-edges} g[src]
// layer flag selects buffers inside device code.
// ---------------------------------------------------------------------------
__global__ __launch_bounds__(256) void gather_kernel(int layer, int n)
{
    int node = (blockIdx.x * blockDim.x + threadIdx.x) >> 5;
    int lane = threadIdx.x & 31;
    if (node >= n) return;

    const float* __restrict__ g = (layer == 0) ? g_g1 : g_g2;
    float* __restrict__ agg = (layer == 0) ? g_agg1 : g_agg2;

    size_t base = (size_t)node * D + lane * 4;
    float4 acc = *(const float4*)(g + base);  // self loop
    int s = g_rowptr[node];
    int e = g_rowptr[node + 1];
    for (int i = s; i < e; i++) {
        int src = g_srcidx[i];  // broadcast load across warp
        float4 v = *(const float4*)(g + (size_t)src * D + lane * 4);
        acc.x += v.x; acc.y += v.y; acc.z += v.z; acc.w += v.w;
    }
    *(float4*)(agg + base) = acc;
}

// ---------------------------------------------------------------------------
// GEMM tiling: 256 threads, 64 (M) x 128 (N=full) tile, K-chunk = 32.
// thread t: tx = t&31 -> 4 consecutive n (float4), ty = t>>5 -> 8 m rows.
// ---------------------------------------------------------------------------

// g1 = (x @ W1) * dinv[m]
__global__ __launch_bounds__(256) void gemm1_kernel(
    const float* __restrict__ A, const float* __restrict__ W, int n)
{
    __shared__ float sW[32 * D];
    __shared__ float sA[64 * 36];
    const int t = threadIdx.x;
    const int tx = t & 31, ty = t >> 5;
    const int m0 = blockIdx.x * 64;

    float acc[8][4];
#pragma unroll
    for (int i = 0; i < 8; i++)
#pragma unroll
        for (int j = 0; j < 4; j++) acc[i][j] = 0.0f;

    for (int kc = 0; kc < D; kc += 32) {
        {
            const float4* src = (const float4*)(W + (size_t)kc * D);
            float4* dst = (float4*)sW;
#pragma unroll
            for (int i = 0; i < 4; i++) dst[t + i * 256] = src[t + i * 256];
        }
#pragma unroll
        for (int s = t; s < 512; s += 256) {
            int r = s >> 3, q = s & 7;
            int m = m0 + r;
            float4 v = make_float4(0.f, 0.f, 0.f, 0.f);
            if (m < n) v = *(const float4*)(A + (size_t)m * D + kc + q * 4);
            *(float4*)(sA + r * 36 + q * 4) = v;
        }
        __syncthreads();
#pragma unroll 4
        for (int k = 0; k < 32; k++) {
            float4 w = *(const float4*)(sW + k * D + tx * 4);
#pragma unroll
            for (int i = 0; i < 8; i++) {
                float a = sA[(ty + 8 * i) * 36 + k];
                acc[i][0] = fmaf(a, w.x, acc[i][0]);
                acc[i][1] = fmaf(a, w.y, acc[i][1]);
                acc[i][2] = fmaf(a, w.z, acc[i][2]);
                acc[i][3] = fmaf(a, w.w, acc[i][3]);
            }
        }
        __syncthreads();
    }

#pragma unroll
    for (int i = 0; i < 8; i++) {
        int m = m0 + ty + 8 * i;
        if (m < n) {
            float dm = g_dinv[m];
            float4 v = make_float4(acc[i][0] * dm, acc[i][1] * dm,
                                   acc[i][2] * dm, acc[i][3] * dm);
            *(float4*)(g_g1 + (size_t)m * D + tx * 4) = v;
        }
    }
}

// x1 = relu(dinv*agg1 + b1) computed on A-load (stored to g_x1);
// g2 = (x1 @ W2) * dinv
__global__ __launch_bounds__(256) void gemm2_kernel(
    const float* __restrict__ W, const float* __restrict__ b1, int n)
{
    __shared__ float sW[32 * D];
    __shared__ float sA[64 * 36];
    __shared__ float sB[D];
    const int t = threadIdx.x;
    const int tx = t & 31, ty = t >> 5;
    const int m0 = blockIdx.x * 64;

    if (t < 32) *(float4*)(sB + t * 4) = *(const float4*)(b1 + t * 4);
    __syncthreads();

    float acc[8][4];
#pragma unroll
    for (int i = 0; i < 8; i++)
#pragma unroll
        for (int j = 0; j < 4; j++) acc[i][j] = 0.0f;

    for (int kc = 0; kc < D; kc += 32) {
        {
            const float4* src = (const float4*)(W + (size_t)kc * D);
            float4* dst = (float4*)sW;
#pragma unroll
            for (int i = 0; i < 4; i++) dst[t + i * 256] = src[t + i * 256];
        }
#pragma unroll
        for (int s = t; s < 512; s += 256) {
            int r = s >> 3, q = s & 7;
            int m = m0 + r;
            int k = kc + q * 4;
            float4 v = make_float4(0.f, 0.f, 0.f, 0.f);
            if (m < n) {
                float4 raw = *(const float4*)(g_agg1 + (size_t)m * D + k);
                float dm = g_dinv[m];
                v.x = fmaxf(fmaf(dm, raw.x, sB[k + 0]), 0.f);
                v.y = fmaxf(fmaf(dm, raw.y, sB[k + 1]), 0.f);
                v.z = fmaxf(fmaf(dm, raw.z, sB[k + 2]), 0.f);
                v.w = fmaxf(fmaf(dm, raw.w, sB[k + 3]), 0.f);
                *(float4*)(g_x1 + (size_t)m * D + k) = v;
            }
            *(float4*)(sA + r * 36 + q * 4) = v;
        }
        __syncthreads();
#pragma unroll 4
        for (int k = 0; k < 32; k++) {
            float4 w = *(const float4*)(sW + k * D + tx * 4);
#pragma unroll
            for (int i = 0; i < 8; i++) {
                float a = sA[(ty + 8 * i) * 36 + k];
                acc[i][0] = fmaf(a, w.x, acc[i][0]);
                acc[i][1] = fmaf(a, w.y, acc[i][1]);
                acc[i][2] = fmaf(a, w.z, acc[i][2]);
                acc[i][3] = fmaf(a, w.w, acc[i][3]);
            }
        }
        __syncthreads();
    }

#pragma unroll
    for (int i = 0; i < 8; i++) {
        int m = m0 + ty + 8 * i;
        if (m < n) {
            float dm = g_dinv[m];
            float4 v = make_float4(acc[i][0] * dm, acc[i][1] * dm,
                                   acc[i][2] * dm, acc[i][3] * dm);
            *(float4*)(g_g2 + (size_t)m * D + tx * 4) = v;
        }
    }
}

// out = [x1 | relu(dinv*agg2 + b2)] @ Wl + bl   (K = 256)
__global__ __launch_bounds__(256) void gemm3_kernel(
    const float* __restrict__ Wl, const float* __restrict__ b2,
    const float* __restrict__ bl, float* __restrict__ out, int n)
{
    __shared__ float sW[32 * D];
    __shared__ float sA[64 * 36];
    __shared__ float sB2[D];
    __shared__ float sBL[D];
    const int t = threadIdx.x;
    const int tx = t & 31, ty = t >> 5;
    const int m0 = blockIdx.x * 64;

    if (t < 32) *(float4*)(sB2 + t * 4) = *(const float4*)(b2 + t * 4);
    else if (t < 64) {
        int q = t - 32;
        *(float4*)(sBL + q * 4) = *(const float4*)(bl + q * 4);
    }
    __syncthreads();

    float acc[8][4];
#pragma unroll
    for (int i = 0; i < 8; i++)
#pragma unroll
        for (int j = 0; j < 4; j++) acc[i][j] = 0.0f;

    for (int kc = 0; kc < 2 * D; kc += 32) {
        {
            const float4* src = (const float4*)(Wl + (size_t)kc * D);
            float4* dst = (float4*)sW;
#pragma unroll
            for (int i = 0; i < 4; i++) dst[t + i * 256] = src[t + i * 256];
        }
#pragma unroll
        for (int s = t; s < 512; s += 256) {
            int r = s >> 3, q = s & 7;
            int m = m0 + r;
            int k = kc + q * 4;          // 0..255, uniform per kc chunk
            float4 v = make_float4(0.f, 0.f, 0.f, 0.f);
            if (m < n) {
                if (k < D) {
                    v = *(const float4*)(g_x1 + (size_t)m * D + k);
                } else {
                    int k2 = k - D;
                    float4 raw = *(const float4*)(g_agg2 + (size_t)m * D + k2);
                    float dm = g_dinv[m];
                    v.x = fmaxf(fmaf(dm, raw.x, sB2[k2 + 0]), 0.f);
                    v.y = fmaxf(fmaf(dm, raw.y, sB2[k2 + 1]), 0.f);
                    v.z = fmaxf(fmaf(dm, raw.z, sB2[k2 + 2]), 0.f);
                    v.w = fmaxf(fmaf(dm, raw.w, sB2[k2 + 3]), 0.f);
                }
            }
            *(float4*)(sA + r * 36 + q * 4) = v;
        }
        __syncthreads();
#pragma unroll 4
        for (int k = 0; k < 32; k++) {
            float4 w = *(const float4*)(sW + k * D + tx * 4);
#pragma unroll
            for (int i = 0; i < 8; i++) {
                float a = sA[(ty + 8 * i) * 36 + k];
                acc[i][0] = fmaf(a, w.x, acc[i][0]);
                acc[i][1] = fmaf(a, w.y, acc[i][1]);
                acc[i][2] = fmaf(a, w.z, acc[i][2]);
                acc[i][3] = fmaf(a, w.w, acc[i][3]);
            }
        }
        __syncthreads();
    }

#pragma unroll
    for (int i = 0; i < 8; i++) {
        int m = m0 + ty + 8 * i;
        if (m < n) {
            float4 v = make_float4(acc[i][0] + sBL[tx * 4 + 0],
                                   acc[i][1] + sBL[tx * 4 + 1],
                                   acc[i][2] + sBL[tx * 4 + 2],
                                   acc[i][3] + sBL[tx * 4 + 3]);
            *(float4*)(out + (size_t)m * D + tx * 4) = v;
        }
    }
}

// ---------------------------------------------------------------------------
// Launch
// ---------------------------------------------------------------------------
extern "C" void kernel_launch(void* const* d_in, const int* in_sizes, int n_in,
                              void* d_out, int out_size)
{
    const float* x  = (const float*)d_in[0];
    const int*   ei = (const int*)d_in[1];      // int32! (JAX x64 disabled)
    const float* W1 = (const float*)d_in[2];
    const float* b1 = (const float*)d_in[3];
    const float* W2 = (const float*)d_in[4];
    const float* b2 = (const float*)d_in[5];
    const float* Wl = (const float*)d_in[6];
    const float* bl = (const float*)d_in[7];
    float* out = (float*)d_out;

    const int n = in_sizes[0] / D;   // 50000
    const int E = in_sizes[1] / 2;   // 600000

    // CSR build (by destination) + dinv
    cnt_zero_kernel<<<(n + 255) / 256, 256>>>(n);
    hist_kernel<<<(E + 255) / 256, 256>>>(ei, E, n);
    scan_kernel<<<1, 1024>>>(n);
    place_kernel<<<(E + 255) / 256, 256>>>(ei, E, n);

    const int gblocks = (n + 63) / 64;
    const int wblocks = (n + 7) / 8;  // one warp per node, 256 thr

    gemm1_kernel<<<gblocks, 256>>>(x, W1, n);
    gather_kernel<<<wblocks, 256>>>(0, n);
    gemm2_kernel<<<gblocks, 256>>>(W2, b1, n);
    gather_kernel<<<wblocks, 256>>>(1, n);
    gemm3_kernel<<<gblocks, 256>>>(Wl, b2, bl, out, n);
}